// round 11
// baseline (speedup 1.0000x reference)
#include <cuda_runtime.h>
#include <cuda_fp16.h>
#include <cstdint>

#define PADK 136           // halfs per smem row (128 + 8 pad) -> conflict-free LDSM
#define FULLMASK 0xffffffffu

// Scratch: per-node transformed features, fp16.
// Y[n, 0:128] = x[n] @ W1a (src half),  Y[n,128:256] = x[n] @ W1b (dst half)
__device__ __half g_Y[(size_t)50000 * 256];
__device__ int g_idx64;

// ---------------------------------------------------------------------------
__device__ __forceinline__ unsigned sptr(const void* p) {
    return (unsigned)__cvta_generic_to_shared(p);
}
__device__ __forceinline__ void ldsm4(unsigned a, unsigned& r0, unsigned& r1,
                                      unsigned& r2, unsigned& r3) {
    asm volatile("ldmatrix.sync.aligned.m8n8.x4.shared.b16 {%0,%1,%2,%3}, [%4];\n"
                 : "=r"(r0), "=r"(r1), "=r"(r2), "=r"(r3) : "r"(a));
}
__device__ __forceinline__ void mma16816(float* c, unsigned a0, unsigned a1,
                                         unsigned a2, unsigned a3,
                                         unsigned b0, unsigned b1) {
    asm volatile(
        "mma.sync.aligned.m16n8k16.row.col.f32.f16.f16.f32 "
        "{%0,%1,%2,%3}, {%4,%5,%6,%7}, {%8,%9}, {%0,%1,%2,%3};\n"
        : "+f"(c[0]), "+f"(c[1]), "+f"(c[2]), "+f"(c[3])
        : "r"(a0), "r"(a1), "r"(a2), "r"(a3), "r"(b0), "r"(b1));
}

// ---------------------------------------------------------------------------
// Warp-level 32x64x128 GEMM.
// ---------------------------------------------------------------------------
__device__ __forceinline__ void warp_mma_32x64(const __half* Aw, const __half* Bw,
                                               float acc[2][8][4], int lane) {
    unsigned a_addr = sptr(Aw + (size_t)(lane & 15) * PADK + ((lane & 16) ? 8 : 0));
    unsigned b_addr = sptr(Bw + (size_t)((lane & 7) + ((lane & 16) ? 8 : 0)) * PADK
                              + ((lane & 8) ? 8 : 0));
    #pragma unroll
    for (int k0 = 0; k0 < 128; k0 += 16) {
        unsigned a0[4], a1[4];
        ldsm4(a_addr + k0 * 2, a0[0], a0[1], a0[2], a0[3]);
        ldsm4(a_addr + 16 * PADK * 2 + k0 * 2, a1[0], a1[1], a1[2], a1[3]);
        #pragma unroll
        for (int np = 0; np < 4; np++) {
            unsigned b0, b1, b2, b3;
            ldsm4(b_addr + (unsigned)(np * 16 * PADK * 2) + k0 * 2, b0, b1, b2, b3);
            mma16816(acc[0][2 * np],     a0[0], a0[1], a0[2], a0[3], b0, b1);
            mma16816(acc[0][2 * np + 1], a0[0], a0[1], a0[2], a0[3], b2, b3);
            mma16816(acc[1][2 * np],     a1[0], a1[1], a1[2], a1[3], b0, b1);
            mma16816(acc[1][2 * np + 1], a1[0], a1[1], a1[2], a1[3], b2, b3);
        }
    }
}

// ---------------------------------------------------------------------------
// Node kernel (persistent, block 256, 2 CTAs/SM):
//   load x tile ONCE, multiply by BOTH W1 halves (staged once in smem).
// ---------------------------------------------------------------------------
__global__ __launch_bounds__(256, 2)
void node_gemm_kernel(const float* __restrict__ x,
                      const float* __restrict__ W1,
                      const void* __restrict__ ei,
                      int n_nodes) {
    extern __shared__ __half smem[];
    __half* As = smem;                    // [128][PADK] single buffer
    __half* Ws = smem + 128 * PADK;       // [256 out-cols][PADK k]

    const int tid = threadIdx.x;

    // edge_index dtype detection (int64 LE small values => odd words all 0)
    if (blockIdx.x == 0 && tid < 32) {
        const unsigned* w = (const unsigned*)ei;
        unsigned v = w[2 * tid + 1] | w[2 * (tid + 32) + 1];
        int any_nz = __any_sync(FULLMASK, v != 0u);
        if (tid == 0) g_idx64 = any_nz ? 0 : 1;
    }

    // Stage BOTH W1 halves once: Ws[c][k] = W1[(k + 128*(c>>7))*128 + (c&127)]
    for (int i = tid; i < 256 * 128; i += 256) {
        int c = i & 255, k = i >> 8;
        Ws[(size_t)c * PADK + k] =
            __float2half(W1[(size_t)(k + ((c >> 7) << 7)) * 128 + (c & 127)]);
    }

    const int warp = tid >> 5, lane = tid & 31;
    const int wm = warp & 3, wn = warp >> 2;   // 4M x 2N
    const int g = lane >> 2, t = lane & 3;
    const int n_tiles = (n_nodes + 127) >> 7;

    __syncthreads();   // Ws staged (also covers detect)

    for (int tile = blockIdx.x; tile < n_tiles; tile += gridDim.x) {
        const int row0 = tile << 7;

        // Load x tile fp32 -> fp16 (coalesced float4, zero-pad OOB rows)
        for (int i = tid; i < 128 * 32; i += 256) {
            int r = i >> 5, c4 = i & 31;
            int gr = row0 + r;
            float4 v = make_float4(0.f, 0.f, 0.f, 0.f);
            if (gr < n_nodes) v = ((const float4*)x)[(size_t)gr * 32 + c4];
            __half* dst = As + (size_t)r * PADK + c4 * 4;
            dst[0] = __float2half(v.x); dst[1] = __float2half(v.y);
            dst[2] = __float2half(v.z); dst[3] = __float2half(v.w);
        }
        __syncthreads();   // A ready

        #pragma unroll
        for (int half_sel = 0; half_sel < 2; half_sel++) {
            float acc[2][8][4];
            #pragma unroll
            for (int mi = 0; mi < 2; mi++)
                #pragma unroll
                for (int n8 = 0; n8 < 8; n8++)
                    acc[mi][n8][0] = acc[mi][n8][1] =
                    acc[mi][n8][2] = acc[mi][n8][3] = 0.f;

            warp_mma_32x64(As + (size_t)(wm * 32) * PADK,
                           Ws + (size_t)(half_sel * 128 + wn * 64) * PADK,
                           acc, lane);

            __half* Yb = g_Y + (half_sel << 7);
            #pragma unroll
            for (int mi = 0; mi < 2; mi++) {
                const int r0 = row0 + wm * 32 + mi * 16 + g;
                #pragma unroll
                for (int n8 = 0; n8 < 8; n8++) {
                    int col = wn * 64 + n8 * 8 + 2 * t;
                    if (r0 < n_nodes)
                        *(__half2*)(Yb + (size_t)r0 * 256 + col) =
                            __floats2half2_rn(acc[mi][n8][0], acc[mi][n8][1]);
                    if (r0 + 8 < n_nodes)
                        *(__half2*)(Yb + (size_t)(r0 + 8) * 256 + col) =
                            __floats2half2_rn(acc[mi][n8][2], acc[mi][n8][3]);
                }
            }
        }
        __syncthreads();   // A fully consumed before next tile's load
    }
}

// ---------------------------------------------------------------------------
// Edge kernel (persistent, block 256, 2 CTAs/SM) — R10 base + software-
// pipelined gather batches (2 batches of LDGs continuously in flight).
// ---------------------------------------------------------------------------
__global__ __launch_bounds__(256, 2)
void edge_kernel(const void* __restrict__ edge_index,
                 const float* __restrict__ b1,
                 const float* __restrict__ W2,
                 const float* __restrict__ b2,
                 float* __restrict__ out,
                 int n_edges) {
    extern __shared__ __half smem[];
    __half* Hs0 = smem;                   // [128][PADK]
    __half* Hs1 = smem + 128 * PADK;
    __half* Ws  = smem + 2 * 128 * PADK;  // [128 n][PADK k] = W2[k][n]

    const int tid = threadIdx.x;
    const int warp = tid >> 5, lane = tid & 31;
    const int wm = warp & 3, wn = warp >> 2;   // 4M x 2N
    const int g = lane >> 2, t = lane & 3;
    const bool oddt = (t & 1);

    // Stage W2 once (transposed; coalesced on global side)
    for (int i = tid; i < 128 * 128; i += 256) {
        int k = i >> 7, n = i & 127;
        Ws[(size_t)n * PADK + k] = __float2half(W2[i]);  // W2[k*128+n]
    }

    // Per-lane constants
    const float4 b1v = *(const float4*)(b1 + lane * 4);
    const __half2 b1h0 = __floats2half2_rn(b1v.x, b1v.y);
    const __half2 b1h1 = __floats2half2_rn(b1v.z, b1v.w);
    const __half2 hzero = __float2half2_rn(0.f);

    int colq[4];
    float4 b2v[4];
    #pragma unroll
    for (int q = 0; q < 4; q++) {
        colq[q] = wn * 64 + 16 * q + (oddt ? 8 + 2 * (t - 1) : 2 * t);
        b2v[q] = *(const float4*)(b2 + colq[q]);
    }

    const int is64 = g_idx64;
    const long long* idx64 = (const long long*)edge_index;
    const int*       idx32 = (const int*)edge_index;
    const int n_tiles = (n_edges + 127) >> 7;

    auto load_idx = [&](int tl) -> int {
        int myE = (tl << 7) + (warp << 4) + (lane & 15);
        if (myE >= n_edges) myE = n_edges - 1;
        size_t off = (lane < 16) ? (size_t)myE : (size_t)n_edges + (size_t)myE;
        return is64 ? (int)idx64[off] : idx32[off];
    };

    int tile = blockIdx.x;
    if (tile >= n_tiles) return;
    int vidx = load_idx(tile);   // prologue index load (covered by Ws staging)

    int li = 0;
    while (true) {
        __half* Hs = (li & 1) ? Hs1 : Hs0;
        const int e0 = tile << 7;

        // ---- warp-cooperative gather, software-pipelined batches of 4 ----
        {
            __half* Hrow = Hs + (size_t)(warp << 4) * PADK + lane * 4;

            auto loadb = [&](int base, uint2* va, uint2* vd) {
                #pragma unroll
                for (int j = 0; j < 4; j++) {
                    int s = __shfl_sync(FULLMASK, vidx, base + j);
                    int d = __shfl_sync(FULLMASK, vidx, 16 + base + j);
                    va[j] = *(const uint2*)(g_Y + (size_t)s * 256 + lane * 4);
                    vd[j] = *(const uint2*)(g_Y + (size_t)d * 256 + 128 + lane * 4);
                }
            };
            auto procb = [&](int base, const uint2* va, const uint2* vd) {
                #pragma unroll
                for (int j = 0; j < 4; j++) {
                    __half2 s0 = *(const __half2*)&va[j].x;
                    __half2 s1 = *(const __half2*)&va[j].y;
                    __half2 d0 = *(const __half2*)&vd[j].x;
                    __half2 d1 = *(const __half2*)&vd[j].y;
                    __half2 r0 = __hmax2(__hadd2(__hadd2(s0, d0), b1h0), hzero);
                    __half2 r1 = __hmax2(__hadd2(__hadd2(s1, d1), b1h1), hzero);
                    uint2 rv;
                    rv.x = *(const unsigned*)&r0;
                    rv.y = *(const unsigned*)&r1;
                    *(uint2*)(Hrow + (size_t)(base + j) * PADK) = rv;
                }
            };

            uint2 vaA[4], vdA[4], vaB[4], vdB[4];
            loadb(0, vaA, vdA);
            loadb(4, vaB, vdB);
            procb(0, vaA, vdA);
            loadb(8, vaA, vdA);
            procb(4, vaB, vdB);
            loadb(12, vaB, vdB);
            procb(8, vaA, vdA);
            procb(12, vaB, vdB);
        }
        __syncthreads();   // H ready; all warps past previous tile's MMA

        // ---- prefetch next tile's indices (latency hidden under MMA) ----
        const int next = tile + gridDim.x;
        const bool more = next < n_tiles;
        int vnext = more ? load_idx(next) : 0;

        // ---- 32x64 warp-tile GEMM ----
        float acc[2][8][4];
        #pragma unroll
        for (int mi = 0; mi < 2; mi++)
            #pragma unroll
            for (int n8 = 0; n8 < 8; n8++)
                acc[mi][n8][0] = acc[mi][n8][1] = acc[mi][n8][2] = acc[mi][n8][3] = 0.f;

        warp_mma_32x64(Hs + (size_t)(wm * 32) * PADK,
                       Ws + (size_t)(wn * 64) * PADK, acc, lane);

        // ---- epilogue: shfl-merge lane pairs -> float4, +b2, STG.128 ----
        #pragma unroll
        for (int mi = 0; mi < 2; mi++) {
            const int r0 = e0 + wm * 32 + mi * 16 + g;
            #pragma unroll
            for (int q = 0; q < 4; q++) {
                const int n8e = 2 * q, n8o = 2 * q + 1;
                float s0 = oddt ? acc[mi][n8e][0] : acc[mi][n8o][0];
                float s1 = oddt ? acc[mi][n8e][1] : acc[mi][n8o][1];
                float s2 = oddt ? acc[mi][n8e][2] : acc[mi][n8o][2];
                float s3 = oddt ? acc[mi][n8e][3] : acc[mi][n8o][3];
                float x0 = __shfl_xor_sync(FULLMASK, s0, 1);
                float x1 = __shfl_xor_sync(FULLMASK, s1, 1);
                float x2 = __shfl_xor_sync(FULLMASK, s2, 1);
                float x3 = __shfl_xor_sync(FULLMASK, s3, 1);
                float4 v0, v1;
                if (!oddt) {
                    v0 = make_float4(acc[mi][n8e][0], acc[mi][n8e][1], x0, x1);
                    v1 = make_float4(acc[mi][n8e][2], acc[mi][n8e][3], x2, x3);
                } else {
                    v0 = make_float4(x0, x1, acc[mi][n8o][0], acc[mi][n8o][1]);
                    v1 = make_float4(x2, x3, acc[mi][n8o][2], acc[mi][n8o][3]);
                }
                v0.x += b2v[q].x; v0.y += b2v[q].y; v0.z += b2v[q].z; v0.w += b2v[q].w;
                v1.x += b2v[q].x; v1.y += b2v[q].y; v1.z += b2v[q].z; v1.w += b2v[q].w;
                if (r0 < n_edges)
                    *(float4*)(out + (size_t)r0 * 128 + colq[q]) = v0;
                if (r0 + 8 < n_edges)
                    *(float4*)(out + (size_t)(r0 + 8) * 128 + colq[q]) = v1;
            }
        }

        if (!more) break;
        tile = next; vidx = vnext; li++;
        // no extra sync: ping-pong H; next gather targets the other buffer
    }
}

// ---------------------------------------------------------------------------
extern "C" void kernel_launch(void* const* d_in, const int* in_sizes, int n_in,
                              void* d_out, int out_size) {
    const float* x  = (const float*)d_in[0];
    const void*  ei = d_in[1];
    const float* W1 = (const float*)d_in[2];
    const float* b1 = (const float*)d_in[3];
    const float* W2 = (const float*)d_in[4];
    const float* b2 = (const float*)d_in[5];
    float* out = (float*)d_out;

    const int n_nodes = in_sizes[0] / 128;
    const int n_edges = in_sizes[1] / 2;

    const int smem3 = 3 * 128 * PADK * (int)sizeof(__half);   // 104448
    static bool attr_set = false;
    if (!attr_set) {
        cudaFuncSetAttribute(node_gemm_kernel,
                             cudaFuncAttributeMaxDynamicSharedMemorySize, smem3);
        cudaFuncSetAttribute(edge_kernel,
                             cudaFuncAttributeMaxDynamicSharedMemorySize, smem3);
        attr_set = true;
    }

    const int node_tiles = (n_nodes + 127) / 128;
    int g1 = node_tiles < 296 ? node_tiles : 296;
    node_gemm_kernel<<<g1, 256, smem3>>>(x, W1, ei, n_nodes);

    const int edge_tiles = (n_edges + 127) / 128;
    int g2 = edge_tiles < 296 ? edge_tiles : 296;
    edge_kernel<<<g2, 256, smem3>>>(ei, b1, W2, b2, out, n_edges);
}